// round 8
// baseline (speedup 1.0000x reference)
#include <cuda_runtime.h>
#include <cuda_bf16.h>

#define LDIM 4096
#define BDIM 32
#define CIN  64
#define ODIM 128
#define KDIM 9
#define CCHUNKS 2               // split-K chunks over channel dim
#define CPER   (CIN / CCHUNKS)  // 32 channels per chunk
#define OCHUNK 64               // outputs per main-kernel block
#define WSTRIDE 10              // packed weight row: {w,w}x9, {bias,bias}

typedef unsigned long long u64;

// Scratch (allocation-free rule: __device__ globals)
__device__ float g_part[CCHUNKS * BDIM * LDIM]; // partial channel sums, 1 MB
__device__ float g_wcn[ODIM * KDIM];            // normalized weight_coeff
__device__ float g_evinv;                       // 1 / ||err_vector||

// ---- packed f32x2 helpers ----
__device__ __forceinline__ u64 pack2(float lo, float hi) {
    u64 r; asm("mov.b64 %0, {%1,%2};" : "=l"(r) : "f"(lo), "f"(hi)); return r;
}
__device__ __forceinline__ u64 ffma2(u64 a, u64 b, u64 c) {
    u64 d; asm("fma.rn.f32x2 %0, %1, %2, %3;" : "=l"(d) : "l"(a), "l"(b), "l"(c));
    return d;
}

// ---------------------------------------------------------------------------
// Kernel A: split-K channel reduction (512 blocks x 128 thr) + prep (block 512)
//   identical to R4 (best measured wallclock)
// ---------------------------------------------------------------------------
__global__ __launch_bounds__(128) void reduce_prep_kernel(
    const float* __restrict__ x,
    const float* __restrict__ wc,
    const float* __restrict__ ev) {

    const int bx = blockIdx.x;
    const int t  = threadIdx.x;

    if (bx < BDIM * 16) {                      // 512 reduce blocks
        const int b   = bx >> 4;               // 0..31
        const int sub = bx & 15;
        const int lt  = sub >> 1;              // l-tile 0..7 (128 float4 each)
        const int cc  = sub & 1;               // channel chunk 0..1
        const int l4  = lt * 128 + t;          // 0..1023

        const float4* xp = reinterpret_cast<const float4*>(x) +
                           ((size_t)b * CIN + cc * CPER) * (LDIM / 4) + l4;
        float4 a0 = make_float4(0.f, 0.f, 0.f, 0.f);
        float4 a1 = make_float4(0.f, 0.f, 0.f, 0.f);
#pragma unroll 8
        for (int i = 0; i < CPER; i += 2) {
            float4 v0 = __ldg(xp + (i    ) * (LDIM / 4));
            float4 v1 = __ldg(xp + (i + 1) * (LDIM / 4));
            a0.x += v0.x; a0.y += v0.y; a0.z += v0.z; a0.w += v0.w;
            a1.x += v1.x; a1.y += v1.y; a1.z += v1.z; a1.w += v1.w;
        }
        a0.x += a1.x; a0.y += a1.y; a0.z += a1.z; a0.w += a1.w;
        reinterpret_cast<float4*>(g_part)[(cc * BDIM + b) * (LDIM / 4) + l4] = a0;
        return;
    }

    // ---- prep block (128 threads) ----
    __shared__ float red[128];
    float ssq = 0.f;
    for (int i = t; i < LDIM; i += 128) { float v = ev[i]; ssq += v * v; }
    red[t] = ssq;
    __syncthreads();
    for (int s = 64; s > 0; s >>= 1) {
        if (t < s) red[t] += red[t + s];
        __syncthreads();
    }
    if (t == 0) g_evinv = rsqrtf(red[0]);

    // one thread per output channel (128 threads = ODIM)
    {
        float w[KDIM];
        float n = 0.f;
#pragma unroll
        for (int k = 0; k < KDIM; ++k) { w[k] = wc[t * KDIM + k]; n += w[k] * w[k]; }
        float inv = rsqrtf(n);
#pragma unroll
        for (int k = 0; k < KDIM; ++k) g_wcn[t * KDIM + k] = w[k] * inv;
    }
}

// ---------------------------------------------------------------------------
// Kernel B: out[b,o,l] = ev[l]/||ev|| * sum_k wcn[o,k]*xs[b, idx[k,l]] + bias[o]
// grid: (8 l-tiles of 512, 32 b, 2 o-chunks of 64) = 512 blocks x 256 thr.
// lpt=2 as one f32x2 lane-pair; o-loop body = 4 LDS + 9 FFMA2 + 1 STG.64.
// Weight smem rows are {w,w} u64 pairs -> LDS broadcasts (1 wavefront each).
// ---------------------------------------------------------------------------
__global__ __launch_bounds__(256) void gmconv_main_kernel(
    const int*   __restrict__ idxm,
    const float* __restrict__ ev,
    const float* __restrict__ bias,
    float*       __restrict__ out) {

    __shared__ float s_xs[LDIM];                    // 16 KB
    __shared__ u64   s_wp[OCHUNK * WSTRIDE];        // 5 KB: {w,w}x9,{bias,bias}

    const int tile  = blockIdx.x;                   // 0..7
    const int b     = blockIdx.y;                   // 0..31
    const int obase = blockIdx.z * OCHUNK;          // 0, 64
    const int t     = threadIdx.x;

    // stage xs[b] = p0 + p1 (L2-resident partials)
    {
        float4* s4 = reinterpret_cast<float4*>(s_xs);
        const float4* g4 = reinterpret_cast<const float4*>(g_part);
#pragma unroll
        for (int i = t; i < LDIM / 4; i += 256) {
            float4 p0 = __ldg(&g4[(0 * BDIM + b) * (LDIM / 4) + i]);
            float4 p1 = __ldg(&g4[(1 * BDIM + b) * (LDIM / 4) + i]);
            s4[i] = make_float4(p0.x + p1.x, p0.y + p1.y,
                                p0.z + p1.z, p0.w + p1.w);
        }
        // packed weight rows: {w0,w0}..{w8,w8},{bias,bias}
#pragma unroll
        for (int i = t; i < OCHUNK * WSTRIDE; i += 256) {
            int o = i / WSTRIDE, s = i - o * WSTRIDE;
            float w = (s < KDIM) ? g_wcn[(obase + o) * KDIM + s]
                                 : bias[obase + o];
            s_wp[i] = pack2(w, w);
        }
    }
    __syncthreads();

    const int l = tile * 512 + t * 2;
    const float evinv = g_evinv;
    float2 e2 = __ldg(reinterpret_cast<const float2*>(ev + l));
    const float ex = e2.x * evinv, ey = e2.y * evinv;

    // gather 9 neighbor pairs from smem, pre-scaled, packed into f32x2
    u64 g2[KDIM];
#pragma unroll
    for (int k = 0; k < KDIM; ++k) {
        int2 id = __ldg(reinterpret_cast<const int2*>(idxm + k * LDIM + l));
        g2[k] = pack2(s_xs[id.x] * ex, s_xs[id.y] * ey);
    }

    float* outp = out + ((size_t)b * ODIM + obase) * LDIM + l;
#pragma unroll 4
    for (int o = 0; o < OCHUNK; ++o) {
        const u64* wp = &s_wp[o * WSTRIDE];
        u64 acc = wp[KDIM];                         // {bias,bias}
#pragma unroll
        for (int k = 0; k < KDIM; ++k)
            acc = ffma2(wp[k], g2[k], acc);
        *reinterpret_cast<u64*>(outp + (size_t)o * LDIM) = acc;  // STG.64
    }
}

// ---------------------------------------------------------------------------
extern "C" void kernel_launch(void* const* d_in, const int* in_sizes, int n_in,
                              void* d_out, int out_size) {
    const float* x    = nullptr;
    const float* wc   = nullptr;
    const float* ev   = nullptr;
    const float* bias = nullptr;
    const int*   idxm = nullptr;

    for (int i = 0; i < n_in; ++i) {
        switch (in_sizes[i]) {
            case BDIM * CIN * LDIM: x    = (const float*)d_in[i]; break;  // 8388608
            case ODIM * KDIM:       wc   = (const float*)d_in[i]; break;  // 1152
            case LDIM:              ev   = (const float*)d_in[i]; break;  // 4096
            case ODIM:              bias = (const float*)d_in[i]; break;  // 128
            case KDIM * LDIM:       idxm = (const int*)  d_in[i]; break;  // 36864
            default: break;
        }
    }

    float* out = (float*)d_out;

    reduce_prep_kernel<<<BDIM * 16 + 1, 128>>>(x, wc, ev);
    gmconv_main_kernel<<<dim3(8, BDIM, 2), 256>>>(idxm, ev, bias, out);
}

// round 9
// speedup vs baseline: 1.2601x; 1.2601x over previous
#include <cuda_runtime.h>
#include <cuda_bf16.h>

#define LDIM 4096
#define BDIM 32
#define CIN  64
#define ODIM 128
#define KDIM 9
#define CCHUNKS 2               // split-K chunks over channel dim
#define CPER   (CIN / CCHUNKS)  // 32 channels per chunk
#define OCHUNK 64               // outputs per main-kernel block

// Scratch (allocation-free rule: __device__ globals)
__device__ float g_part[CCHUNKS * BDIM * LDIM]; // partial channel sums, 1 MB
__device__ float g_wcn[ODIM * KDIM];            // normalized weight_coeff
__device__ float g_bias[ODIM];                  // staged bias
__device__ float g_evinv;                       // 1 / ||err_vector||

// Constant-bank weights: read via LDC/LDCU (separate port, zero L1 traffic)
__constant__ float c_w[ODIM * KDIM];            // 4.6 KB
__constant__ float c_b[ODIM];                   // 0.5 KB

// ---------------------------------------------------------------------------
// Kernel A: split-K channel reduction (512 blocks x 128 thr) + prep (block 512)
// ---------------------------------------------------------------------------
__global__ __launch_bounds__(128) void reduce_prep_kernel(
    const float* __restrict__ x,
    const float* __restrict__ wc,
    const float* __restrict__ ev,
    const float* __restrict__ bias) {

    const int bx = blockIdx.x;
    const int t  = threadIdx.x;

    if (bx < BDIM * 16) {                      // 512 reduce blocks
        const int b   = bx >> 4;               // 0..31
        const int sub = bx & 15;
        const int lt  = sub >> 1;              // l-tile 0..7 (128 float4 each)
        const int cc  = sub & 1;               // channel chunk 0..1
        const int l4  = lt * 128 + t;          // 0..1023

        const float4* xp = reinterpret_cast<const float4*>(x) +
                           ((size_t)b * CIN + cc * CPER) * (LDIM / 4) + l4;
        float4 a0 = make_float4(0.f, 0.f, 0.f, 0.f);
        float4 a1 = make_float4(0.f, 0.f, 0.f, 0.f);
#pragma unroll 8
        for (int i = 0; i < CPER; i += 2) {
            float4 v0 = __ldg(xp + (i    ) * (LDIM / 4));
            float4 v1 = __ldg(xp + (i + 1) * (LDIM / 4));
            a0.x += v0.x; a0.y += v0.y; a0.z += v0.z; a0.w += v0.w;
            a1.x += v1.x; a1.y += v1.y; a1.z += v1.z; a1.w += v1.w;
        }
        a0.x += a1.x; a0.y += a1.y; a0.z += a1.z; a0.w += a1.w;
        reinterpret_cast<float4*>(g_part)[(cc * BDIM + b) * (LDIM / 4) + l4] = a0;
        return;
    }

    // ---- prep block (128 threads) ----
    __shared__ float red[128];
    float ssq = 0.f;
    for (int i = t; i < LDIM; i += 128) { float v = ev[i]; ssq += v * v; }
    red[t] = ssq;
    __syncthreads();
    for (int s = 64; s > 0; s >>= 1) {
        if (t < s) red[t] += red[t + s];
        __syncthreads();
    }
    if (t == 0) g_evinv = rsqrtf(red[0]);

    // one thread per output channel (128 threads = ODIM)
    {
        float w[KDIM];
        float n = 0.f;
#pragma unroll
        for (int k = 0; k < KDIM; ++k) { w[k] = wc[t * KDIM + k]; n += w[k] * w[k]; }
        float inv = rsqrtf(n);
#pragma unroll
        for (int k = 0; k < KDIM; ++k) g_wcn[t * KDIM + k] = w[k] * inv;
        g_bias[t] = bias[t];
    }
}

// ---------------------------------------------------------------------------
// Kernel B: out[b,o,l] = ev[l]/||ev|| * sum_k c_w[o,k]*xs[b, idx[k,l]] + c_b[o]
// grid: (8 l-tiles of 512, 32 b, 2 o-chunks of 64) = 512 blocks x 256 thr.
// Weights/bias from the constant bank (LDC/LDCU) -> o-loop does ZERO smem LDS.
// __stcs output stores keep x L2-resident for the next replay's reduce.
// ---------------------------------------------------------------------------
__global__ __launch_bounds__(256) void gmconv_main_kernel(
    const int*   __restrict__ idxm,
    const float* __restrict__ ev,
    float*       __restrict__ out) {

    __shared__ float s_xs[LDIM];                    // 16 KB (only smem)

    const int tile  = blockIdx.x;                   // 0..7
    const int b     = blockIdx.y;                   // 0..31
    const int obase = blockIdx.z * OCHUNK;          // 0, 64
    const int t     = threadIdx.x;

    // stage xs[b] = p0 + p1 (L2-resident partials)
    {
        float4* s4 = reinterpret_cast<float4*>(s_xs);
        const float4* g4 = reinterpret_cast<const float4*>(g_part);
#pragma unroll
        for (int i = t; i < LDIM / 4; i += 256) {
            float4 p0 = __ldg(&g4[(0 * BDIM + b) * (LDIM / 4) + i]);
            float4 p1 = __ldg(&g4[(1 * BDIM + b) * (LDIM / 4) + i]);
            s4[i] = make_float4(p0.x + p1.x, p0.y + p1.y,
                                p0.z + p1.z, p0.w + p1.w);
        }
    }
    __syncthreads();

    const int l = tile * 512 + t * 2;
    const float evinv = g_evinv;
    float2 e2 = __ldg(reinterpret_cast<const float2*>(ev + l));
    const float ex = e2.x * evinv, ey = e2.y * evinv;

    // gather 9 neighbor pairs from smem, pre-scaled
    float gx[KDIM], gy[KDIM];
#pragma unroll
    for (int k = 0; k < KDIM; ++k) {
        int2 id = __ldg(reinterpret_cast<const int2*>(idxm + k * LDIM + l));
        gx[k] = s_xs[id.x] * ex;
        gy[k] = s_xs[id.y] * ey;
    }

    float* outp = out + ((size_t)b * ODIM + obase) * LDIM + l;
#pragma unroll 4
    for (int o = 0; o < OCHUNK; ++o) {
        const float bo = c_b[obase + o];            // LDC (const port)
        float rx = bo, ry = bo;
#pragma unroll
        for (int k = 0; k < KDIM; ++k) {
            const float w = c_w[(obase + o) * KDIM + k];   // LDC, uniform
            rx = fmaf(w, gx[k], rx);
            ry = fmaf(w, gy[k], ry);
        }
        __stcs(reinterpret_cast<float2*>(outp + (size_t)o * LDIM),
               make_float2(rx, ry));                // streaming STG.64
    }
}

// ---------------------------------------------------------------------------
extern "C" void kernel_launch(void* const* d_in, const int* in_sizes, int n_in,
                              void* d_out, int out_size) {
    const float* x    = nullptr;
    const float* wc   = nullptr;
    const float* ev   = nullptr;
    const float* bias = nullptr;
    const int*   idxm = nullptr;

    for (int i = 0; i < n_in; ++i) {
        switch (in_sizes[i]) {
            case BDIM * CIN * LDIM: x    = (const float*)d_in[i]; break;  // 8388608
            case ODIM * KDIM:       wc   = (const float*)d_in[i]; break;  // 1152
            case LDIM:              ev   = (const float*)d_in[i]; break;  // 4096
            case ODIM:              bias = (const float*)d_in[i]; break;  // 128
            case KDIM * LDIM:       idxm = (const int*)  d_in[i]; break;  // 36864
            default: break;
        }
    }

    float* out = (float*)d_out;

    reduce_prep_kernel<<<BDIM * 16 + 1, 128>>>(x, wc, ev, bias);

    // Stage normalized weights + bias into the constant bank (graph-capturable
    // D2D memcpy nodes, ordered after prep on the same stream).
    void* wsrc = nullptr; void* bsrc = nullptr;
    cudaGetSymbolAddress(&wsrc, g_wcn);
    cudaGetSymbolAddress(&bsrc, g_bias);
    cudaMemcpyToSymbolAsync(c_w, wsrc, ODIM * KDIM * sizeof(float), 0,
                            cudaMemcpyDeviceToDevice, 0);
    cudaMemcpyToSymbolAsync(c_b, bsrc, ODIM * sizeof(float), 0,
                            cudaMemcpyDeviceToDevice, 0);

    gmconv_main_kernel<<<dim3(8, BDIM, 2), 256>>>(idxm, ev, out);
}

// round 10
// speedup vs baseline: 1.3552x; 1.0755x over previous
#include <cuda_runtime.h>
#include <cuda_bf16.h>

#define LDIM 4096
#define BDIM 32
#define CIN  64
#define ODIM 128
#define KDIM 9
#define CCHUNKS 2               // split-K chunks over channel dim
#define CPER   (CIN / CCHUNKS)  // 32 channels per chunk
#define OCHUNK 64               // outputs per main-kernel block
#define WSTRIDE 12              // padded row: w0..w8, bias, 0, 0

typedef unsigned long long u64;

// Scratch (allocation-free rule: __device__ globals)
__device__ float g_part[CCHUNKS * BDIM * LDIM]; // partial channel sums, 1 MB
__device__ float g_wb[ODIM * WSTRIDE];          // padded normalized w + bias
__device__ float g_evinv;                       // 1 / ||err_vector||

// Constant bank: same padded layout, viewed as float4 rows (3 per o) -> LDC.128
__constant__ float4 c_wb4[ODIM * 3];            // 6 KB

// ---- packed f32x2 helpers ----
__device__ __forceinline__ u64 pack2(float lo, float hi) {
    u64 r; asm("mov.b64 %0, {%1,%2};" : "=l"(r) : "f"(lo), "f"(hi)); return r;
}
__device__ __forceinline__ u64 ffma2(u64 a, u64 b, u64 c) {
    u64 d; asm("fma.rn.f32x2 %0, %1, %2, %3;" : "=l"(d) : "l"(a), "l"(b), "l"(c));
    return d;
}
__device__ __forceinline__ float2 unpack2(u64 v) {
    float2 f; asm("mov.b64 {%0,%1}, %2;" : "=f"(f.x), "=f"(f.y) : "l"(v)); return f;
}

// ---------------------------------------------------------------------------
// Kernel A: split-K channel reduction (512 blocks x 128 thr) + prep (block 512)
// ---------------------------------------------------------------------------
__global__ __launch_bounds__(128) void reduce_prep_kernel(
    const float* __restrict__ x,
    const float* __restrict__ wc,
    const float* __restrict__ ev,
    const float* __restrict__ bias) {

    const int bx = blockIdx.x;
    const int t  = threadIdx.x;

    if (bx < BDIM * 16) {                      // 512 reduce blocks
        const int b   = bx >> 4;               // 0..31
        const int sub = bx & 15;
        const int lt  = sub >> 1;              // l-tile 0..7 (128 float4 each)
        const int cc  = sub & 1;               // channel chunk 0..1
        const int l4  = lt * 128 + t;          // 0..1023

        const float4* xp = reinterpret_cast<const float4*>(x) +
                           ((size_t)b * CIN + cc * CPER) * (LDIM / 4) + l4;
        float4 a0 = make_float4(0.f, 0.f, 0.f, 0.f);
        float4 a1 = make_float4(0.f, 0.f, 0.f, 0.f);
#pragma unroll 8
        for (int i = 0; i < CPER; i += 2) {
            float4 v0 = __ldg(xp + (i    ) * (LDIM / 4));
            float4 v1 = __ldg(xp + (i + 1) * (LDIM / 4));
            a0.x += v0.x; a0.y += v0.y; a0.z += v0.z; a0.w += v0.w;
            a1.x += v1.x; a1.y += v1.y; a1.z += v1.z; a1.w += v1.w;
        }
        a0.x += a1.x; a0.y += a1.y; a0.z += a1.z; a0.w += a1.w;
        reinterpret_cast<float4*>(g_part)[(cc * BDIM + b) * (LDIM / 4) + l4] = a0;
        return;
    }

    // ---- prep block (128 threads) ----
    __shared__ float red[128];
    float ssq = 0.f;
    for (int i = t; i < LDIM; i += 128) { float v = ev[i]; ssq += v * v; }
    red[t] = ssq;
    __syncthreads();
    for (int s = 64; s > 0; s >>= 1) {
        if (t < s) red[t] += red[t + s];
        __syncthreads();
    }
    if (t == 0) g_evinv = rsqrtf(red[0]);

    // one thread per output channel (128 threads = ODIM); padded 12-row
    {
        float w[KDIM];
        float n = 0.f;
#pragma unroll
        for (int k = 0; k < KDIM; ++k) { w[k] = wc[t * KDIM + k]; n += w[k] * w[k]; }
        float inv = rsqrtf(n);
#pragma unroll
        for (int k = 0; k < KDIM; ++k) g_wb[t * WSTRIDE + k] = w[k] * inv;
        g_wb[t * WSTRIDE + 9]  = bias[t];
        g_wb[t * WSTRIDE + 10] = 0.f;
        g_wb[t * WSTRIDE + 11] = 0.f;
    }
}

// ---------------------------------------------------------------------------
// Kernel B: out[b,o,l] = ev[l]/||ev|| * sum_k w[o,k]*xs[b, idx[k,l]] + bias[o]
// grid: (4 l-tiles of 1024, 32 b, 2 o-chunks of 64) = 256 blocks x 256 thr.
// lpt=4 as two f32x2 lane-pairs. Weights via 3x LDC.128 per o, packed {w,w}
// in REGISTERS (zero smem traffic in o-loop). STG.128 streaming stores.
// ---------------------------------------------------------------------------
__global__ __launch_bounds__(256) void gmconv_main_kernel(
    const int*   __restrict__ idxm,
    const float* __restrict__ ev,
    float*       __restrict__ out) {

    __shared__ float s_xs[LDIM];                    // 16 KB (only smem)

    const int tile  = blockIdx.x;                   // 0..3
    const int b     = blockIdx.y;                   // 0..31
    const int obase = blockIdx.z * OCHUNK;          // 0, 64
    const int t     = threadIdx.x;

    // stage xs[b] = p0 + p1 (L2-resident partials)
    {
        float4* s4 = reinterpret_cast<float4*>(s_xs);
        const float4* g4 = reinterpret_cast<const float4*>(g_part);
#pragma unroll
        for (int i = t; i < LDIM / 4; i += 256) {
            float4 p0 = __ldg(&g4[(0 * BDIM + b) * (LDIM / 4) + i]);
            float4 p1 = __ldg(&g4[(1 * BDIM + b) * (LDIM / 4) + i]);
            s4[i] = make_float4(p0.x + p1.x, p0.y + p1.y,
                                p0.z + p1.z, p0.w + p1.w);
        }
    }
    __syncthreads();

    const int l = tile * 1024 + t * 4;
    const float evinv = g_evinv;
    float4 e4 = __ldg(reinterpret_cast<const float4*>(ev + l));
    const float ex = e4.x * evinv, ey = e4.y * evinv,
                ez = e4.z * evinv, ew = e4.w * evinv;

    // gather 9 neighbor quads from smem, pre-scaled, packed into f32x2 pairs
    u64 g01[KDIM], g23[KDIM];
#pragma unroll
    for (int k = 0; k < KDIM; ++k) {
        int4 id = __ldg(reinterpret_cast<const int4*>(idxm + k * LDIM + l));
        g01[k] = pack2(s_xs[id.x] * ex, s_xs[id.y] * ey);
        g23[k] = pack2(s_xs[id.z] * ez, s_xs[id.w] * ew);
    }

    float* outp = out + ((size_t)b * ODIM + obase) * LDIM + l;
#pragma unroll 2
    for (int o = 0; o < OCHUNK; ++o) {
        // 3x LDC.128: w0..w3 | w4..w7 | w8, bias, 0, 0
        const float4 wa = c_wb4[(obase + o) * 3 + 0];
        const float4 wb = c_wb4[(obase + o) * 3 + 1];
        const float4 wc = c_wb4[(obase + o) * 3 + 2];

        u64 wp[KDIM];
        wp[0] = pack2(wa.x, wa.x); wp[1] = pack2(wa.y, wa.y);
        wp[2] = pack2(wa.z, wa.z); wp[3] = pack2(wa.w, wa.w);
        wp[4] = pack2(wb.x, wb.x); wp[5] = pack2(wb.y, wb.y);
        wp[6] = pack2(wb.z, wb.z); wp[7] = pack2(wb.w, wb.w);
        wp[8] = pack2(wc.x, wc.x);
        const u64 bb = pack2(wc.y, wc.y);

        u64 acc01 = bb, acc23 = bb;
#pragma unroll
        for (int k = 0; k < KDIM; ++k) {
            acc01 = ffma2(wp[k], g01[k], acc01);
            acc23 = ffma2(wp[k], g23[k], acc23);
        }
        float2 r01 = unpack2(acc01);
        float2 r23 = unpack2(acc23);
        __stcs(reinterpret_cast<float4*>(outp + (size_t)o * LDIM),
               make_float4(r01.x, r01.y, r23.x, r23.y));   // streaming STG.128
    }
}

// ---------------------------------------------------------------------------
extern "C" void kernel_launch(void* const* d_in, const int* in_sizes, int n_in,
                              void* d_out, int out_size) {
    const float* x    = nullptr;
    const float* wc   = nullptr;
    const float* ev   = nullptr;
    const float* bias = nullptr;
    const int*   idxm = nullptr;

    for (int i = 0; i < n_in; ++i) {
        switch (in_sizes[i]) {
            case BDIM * CIN * LDIM: x    = (const float*)d_in[i]; break;  // 8388608
            case ODIM * KDIM:       wc   = (const float*)d_in[i]; break;  // 1152
            case LDIM:              ev   = (const float*)d_in[i]; break;  // 4096
            case ODIM:              bias = (const float*)d_in[i]; break;  // 128
            case KDIM * LDIM:       idxm = (const int*)  d_in[i]; break;  // 36864
            default: break;
        }
    }

    float* out = (float*)d_out;

    reduce_prep_kernel<<<BDIM * 16 + 1, 128>>>(x, wc, ev, bias);

    // ONE graph-capturable D2D memcpy node: padded weights+bias -> const bank
    void* wsrc = nullptr;
    cudaGetSymbolAddress(&wsrc, g_wb);
    cudaMemcpyToSymbolAsync(c_wb4, wsrc, ODIM * WSTRIDE * sizeof(float), 0,
                            cudaMemcpyDeviceToDevice, 0);

    gmconv_main_kernel<<<dim3(4, BDIM, 2), 256>>>(idxm, ev, out);
}

// round 11
// speedup vs baseline: 1.3745x; 1.0142x over previous
#include <cuda_runtime.h>
#include <cuda_bf16.h>

#define LDIM 4096
#define BDIM 32
#define CIN  64
#define ODIM 128
#define KDIM 9
#define CCHUNKS 2               // split-K chunks over channel dim
#define CPER   (CIN / CCHUNKS)  // 32 channels per chunk
#define OCHUNK 64               // outputs per main-kernel block
#define WSTRIDE 12              // padded row: w0..w8, bias, 0, 0

typedef unsigned long long u64;

// Scratch (allocation-free rule: __device__ globals)
__device__ float g_part[CCHUNKS * BDIM * LDIM]; // partial channel sums, 1 MB
__device__ float g_wb[ODIM * WSTRIDE];          // padded normalized w + bias
__device__ float g_evinv;                       // 1 / ||err_vector||

// Constant bank: padded rows viewed as float4 (3 per o) -> LDC.128
__constant__ float4 c_wb4[ODIM * 3];            // 6 KB

// ---- packed f32x2 helpers ----
__device__ __forceinline__ u64 pack2(float lo, float hi) {
    u64 r; asm("mov.b64 %0, {%1,%2};" : "=l"(r) : "f"(lo), "f"(hi)); return r;
}
__device__ __forceinline__ u64 ffma2(u64 a, u64 b, u64 c) {
    u64 d; asm("fma.rn.f32x2 %0, %1, %2, %3;" : "=l"(d) : "l"(a), "l"(b), "l"(c));
    return d;
}
__device__ __forceinline__ float2 unpack2(u64 v) {
    float2 f; asm("mov.b64 {%0,%1}, %2;" : "=f"(f.x), "=f"(f.y) : "l"(v)); return f;
}

// ---------------------------------------------------------------------------
// Kernel A: split-K channel reduction (512 blocks x 128 thr) + prep (block 512)
// ---------------------------------------------------------------------------
__global__ __launch_bounds__(128) void reduce_prep_kernel(
    const float* __restrict__ x,
    const float* __restrict__ wc,
    const float* __restrict__ ev,
    const float* __restrict__ bias) {

    const int bx = blockIdx.x;
    const int t  = threadIdx.x;

    if (bx < BDIM * 16) {                      // 512 reduce blocks
        const int b   = bx >> 4;               // 0..31
        const int sub = bx & 15;
        const int lt  = sub >> 1;              // l-tile 0..7 (128 float4 each)
        const int cc  = sub & 1;               // channel chunk 0..1
        const int l4  = lt * 128 + t;          // 0..1023

        const float4* xp = reinterpret_cast<const float4*>(x) +
                           ((size_t)b * CIN + cc * CPER) * (LDIM / 4) + l4;
        float4 a0 = make_float4(0.f, 0.f, 0.f, 0.f);
        float4 a1 = make_float4(0.f, 0.f, 0.f, 0.f);
#pragma unroll 8
        for (int i = 0; i < CPER; i += 2) {
            float4 v0 = __ldg(xp + (i    ) * (LDIM / 4));
            float4 v1 = __ldg(xp + (i + 1) * (LDIM / 4));
            a0.x += v0.x; a0.y += v0.y; a0.z += v0.z; a0.w += v0.w;
            a1.x += v1.x; a1.y += v1.y; a1.z += v1.z; a1.w += v1.w;
        }
        a0.x += a1.x; a0.y += a1.y; a0.z += a1.z; a0.w += a1.w;
        reinterpret_cast<float4*>(g_part)[(cc * BDIM + b) * (LDIM / 4) + l4] = a0;
        return;
    }

    // ---- prep block (128 threads) ----
    __shared__ float red[128];
    float ssq = 0.f;
    for (int i = t; i < LDIM; i += 128) { float v = ev[i]; ssq += v * v; }
    red[t] = ssq;
    __syncthreads();
    for (int s = 64; s > 0; s >>= 1) {
        if (t < s) red[t] += red[t + s];
        __syncthreads();
    }
    if (t == 0) g_evinv = rsqrtf(red[0]);

    // one thread per output channel (128 threads = ODIM); padded 12-row
    {
        float w[KDIM];
        float n = 0.f;
#pragma unroll
        for (int k = 0; k < KDIM; ++k) { w[k] = wc[t * KDIM + k]; n += w[k] * w[k]; }
        float inv = rsqrtf(n);
#pragma unroll
        for (int k = 0; k < KDIM; ++k) g_wb[t * WSTRIDE + k] = w[k] * inv;
        g_wb[t * WSTRIDE + 9]  = bias[t];
        g_wb[t * WSTRIDE + 10] = 0.f;
        g_wb[t * WSTRIDE + 11] = 0.f;
    }
}

// ---------------------------------------------------------------------------
// Kernel B: out[b,o,l] = ev[l]/||ev|| * sum_k w[o,k]*xs[b, idx[k,l]] + bias[o]
// grid: (4 l-tiles of 1024, 32 b, 2 o-chunks of 64) = 256 blocks x 256 thr.
// lpt=4, two f32x2 accumulators per o. o-loop in groups of 4: 12 LDC.128
// hoisted up front, then 4 independent FFMA2 chains (8 accs in flight).
// ---------------------------------------------------------------------------
__global__ __launch_bounds__(256, 2) void gmconv_main_kernel(
    const int*   __restrict__ idxm,
    const float* __restrict__ ev,
    float*       __restrict__ out) {

    __shared__ float s_xs[LDIM];                    // 16 KB (only smem)

    const int tile  = blockIdx.x;                   // 0..3
    const int b     = blockIdx.y;                   // 0..31
    const int obase = blockIdx.z * OCHUNK;          // 0, 64
    const int t     = threadIdx.x;

    // stage xs[b] = p0 + p1 (L2-resident partials)
    {
        float4* s4 = reinterpret_cast<float4*>(s_xs);
        const float4* g4 = reinterpret_cast<const float4*>(g_part);
#pragma unroll
        for (int i = t; i < LDIM / 4; i += 256) {
            float4 p0 = __ldg(&g4[(0 * BDIM + b) * (LDIM / 4) + i]);
            float4 p1 = __ldg(&g4[(1 * BDIM + b) * (LDIM / 4) + i]);
            s4[i] = make_float4(p0.x + p1.x, p0.y + p1.y,
                                p0.z + p1.z, p0.w + p1.w);
        }
    }
    __syncthreads();

    const int l = tile * 1024 + t * 4;
    const float evinv = g_evinv;
    float4 e4 = __ldg(reinterpret_cast<const float4*>(ev + l));
    const float ex = e4.x * evinv, ey = e4.y * evinv,
                ez = e4.z * evinv, ew = e4.w * evinv;

    // gather 9 neighbor quads from smem, pre-scaled, packed into f32x2 pairs
    u64 g01[KDIM], g23[KDIM];
#pragma unroll
    for (int k = 0; k < KDIM; ++k) {
        int4 id = __ldg(reinterpret_cast<const int4*>(idxm + k * LDIM + l));
        g01[k] = pack2(s_xs[id.x] * ex, s_xs[id.y] * ey);
        g23[k] = pack2(s_xs[id.z] * ez, s_xs[id.w] * ew);
    }

    const float4* wq = &c_wb4[obase * 3];
    float* outp = out + ((size_t)b * ODIM + obase) * LDIM + l;

#pragma unroll 2
    for (int og = 0; og < OCHUNK; og += 4) {
        // hoist 12 LDC.128 (weights+bias for 4 output channels)
        float4 q[12];
#pragma unroll
        for (int j = 0; j < 12; ++j) q[j] = wq[og * 3 + j];

        // 4 independent dual-accumulator chains
        u64 acc01[4], acc23[4];
#pragma unroll
        for (int j = 0; j < 4; ++j) {
            const u64 bb = pack2(q[j * 3 + 2].y, q[j * 3 + 2].y);
            acc01[j] = bb; acc23[j] = bb;
        }
#pragma unroll
        for (int k = 0; k < KDIM; ++k) {
            // weight k for channel j lives in q[j*3 + k/4] component k%4
#pragma unroll
            for (int j = 0; j < 4; ++j) {
                const float* qf = reinterpret_cast<const float*>(&q[j * 3]);
                const u64 w2 = pack2(qf[k], qf[k]);
                acc01[j] = ffma2(w2, g01[k], acc01[j]);
                acc23[j] = ffma2(w2, g23[k], acc23[j]);
            }
        }
#pragma unroll
        for (int j = 0; j < 4; ++j) {
            float2 r01 = unpack2(acc01[j]);
            float2 r23 = unpack2(acc23[j]);
            __stcs(reinterpret_cast<float4*>(outp),
                   make_float4(r01.x, r01.y, r23.x, r23.y));
            outp += LDIM;                        // pointer step, no IMAD chain
        }
    }
}

// ---------------------------------------------------------------------------
extern "C" void kernel_launch(void* const* d_in, const int* in_sizes, int n_in,
                              void* d_out, int out_size) {
    const float* x    = nullptr;
    const float* wc   = nullptr;
    const float* ev   = nullptr;
    const float* bias = nullptr;
    const int*   idxm = nullptr;

    for (int i = 0; i < n_in; ++i) {
        switch (in_sizes[i]) {
            case BDIM * CIN * LDIM: x    = (const float*)d_in[i]; break;  // 8388608
            case ODIM * KDIM:       wc   = (const float*)d_in[i]; break;  // 1152
            case LDIM:              ev   = (const float*)d_in[i]; break;  // 4096
            case ODIM:              bias = (const float*)d_in[i]; break;  // 128
            case KDIM * LDIM:       idxm = (const int*)  d_in[i]; break;  // 36864
            default: break;
        }
    }

    float* out = (float*)d_out;

    reduce_prep_kernel<<<BDIM * 16 + 1, 128>>>(x, wc, ev, bias);

    // ONE graph-capturable D2D memcpy node: padded weights+bias -> const bank
    void* wsrc = nullptr;
    cudaGetSymbolAddress(&wsrc, g_wb);
    cudaMemcpyToSymbolAsync(c_wb4, wsrc, ODIM * WSTRIDE * sizeof(float), 0,
                            cudaMemcpyDeviceToDevice, 0);

    gmconv_main_kernel<<<dim3(4, BDIM, 2), 256>>>(idxm, ev, out);
}